// round 17
// baseline (speedup 1.0000x reference)
#include <cuda_runtime.h>
#include <cuda_fp16.h>
#include <cstdint>

// Problem constants
#define Bn 4
#define Tn 64
#define Fn 32
#define Nn 512
#define Hn 64
#define SROWS 288
#define COLS_PER_CTA 16
#define CTAS_PER_B 32
#define NCTAS (Bn * CTAS_PER_B)   // 128 CTAs, 1/SM
#define NTHREADS 256
#define MB 64                     // k-chunk width (halves)
#define NCHUNK (Nn / MB)          // 8
#define NBUF 3                    // state ring depth

#define CPITCH_H 72               // chunk row pitch halves (144B: 16 mod 128 -> LDSM conflict-free)
#define CPITCH_W 36
#define PITCH_SST_H 520           // S^T pitch halves (1040B)
#define PITCH_SST_W 260
#define PV_H 392                  // sV / sW pitch halves (784B)
#define PV_W 196
#define NV 384

#define CHUNK_HALVES (SROWS * CPITCH_H)     // 20736
#define CHUNK_BYTES  (CHUNK_HALVES * 2)     // 41472
#define CHUNK_WORDS  (CHUNK_HALVES / 2)     // 10368

// smem layout (float offsets)
#define OFF_MBAR   0                        // 8 floats (3 x 8B mbarriers + pad)
#define OFF_STATE  8                        // 3*10368 words
#define OFF_SST    31112                    // 16*260 words (fp16 S^T)
#define OFF_V      35272                    // 16*196 words (fp16 V col-major)
#define OFF_W      38408                    // 64*196 words (fp16 weights)
#define OFF_BIAS   50952                    // 64 floats
#define SMEM_FLOATS 51016
#define SMEM_BYTES  (SMEM_FLOATS * 4)       // 204064

// Persistent global state: fp16, chunk-major, rows padded to CPITCH_H halves.
__device__ __align__(16) __half g_state[2][Bn][NCHUNK][SROWS][CPITCH_H];
__device__ unsigned g_count = 0;
__device__ unsigned g_sense = 0;

__device__ __forceinline__ void grid_barrier(unsigned* lsense) {
    __syncthreads();
    if (threadIdx.x == 0) {
        __threadfence();
        unsigned s = (*lsense) ^ 1u;
        *lsense = s;
        unsigned old = atomicAdd(&g_count, 1u);
        if (old == NCTAS - 1u) {
            atomicExch(&g_count, 0u);
            __threadfence();
            atomicExch(&g_sense, s);
        } else {
            while (atomicAdd(&g_sense, 0u) != s) { __nanosleep(64); }
            __threadfence();
        }
    }
    __syncthreads();
}

// mma.sync m16n8k16 f16 with f32 accumulate
__device__ __forceinline__ void mma_f16(float& d0, float& d1, float& d2, float& d3,
                                        uint32_t a0, uint32_t a1, uint32_t a2, uint32_t a3,
                                        uint32_t b0, uint32_t b1) {
    asm volatile(
        "mma.sync.aligned.m16n8k16.row.col.f32.f16.f16.f32 "
        "{%0,%1,%2,%3}, {%4,%5,%6,%7}, {%8,%9}, {%0,%1,%2,%3};"
        : "+f"(d0), "+f"(d1), "+f"(d2), "+f"(d3)
        : "r"(a0), "r"(a1), "r"(a2), "r"(a3), "r"(b0), "r"(b1));
}

// ldmatrix wrappers (sm_75+ PTX)
__device__ __forceinline__ void ldsm_x4(uint32_t& r0, uint32_t& r1, uint32_t& r2,
                                        uint32_t& r3, uint32_t addr) {
    asm volatile("ldmatrix.sync.aligned.m8n8.x4.shared.b16 {%0,%1,%2,%3}, [%4];"
                 : "=r"(r0), "=r"(r1), "=r"(r2), "=r"(r3) : "r"(addr));
}
__device__ __forceinline__ void ldsm_x2(uint32_t& r0, uint32_t& r1, uint32_t addr) {
    asm volatile("ldmatrix.sync.aligned.m8n8.x2.shared.b16 {%0,%1}, [%2];"
                 : "=r"(r0), "=r"(r1) : "r"(addr));
}

// mbarrier helpers
__device__ __forceinline__ void mbar_init(uint32_t addr, uint32_t count) {
    asm volatile("mbarrier.init.shared.b64 [%0], %1;" :: "r"(addr), "r"(count) : "memory");
}
__device__ __forceinline__ void mbar_expect_tx(uint32_t addr, uint32_t bytes) {
    asm volatile("mbarrier.arrive.expect_tx.shared.b64 _, [%0], %1;"
                 :: "r"(addr), "r"(bytes) : "memory");
}
__device__ __forceinline__ void mbar_wait(uint32_t addr, uint32_t parity) {
    uint32_t done;
    asm volatile(
        "{\n\t.reg .pred p;\n\t"
        "mbarrier.try_wait.parity.acquire.cta.shared::cta.b64 p, [%1], %2;\n\t"
        "selp.b32 %0, 1, 0, p;\n\t}"
        : "=r"(done) : "r"(addr), "r"(parity) : "memory");
    if (!done) {
        asm volatile(
            "{\n\t.reg .pred P1;\n\t"
            "WL_%=:\n\t"
            "mbarrier.try_wait.parity.acquire.cta.shared::cta.b64 P1, [%0], %1, 0x989680;\n\t"
            "@P1 bra.uni WD_%=;\n\t"
            "bra.uni WL_%=;\n\t"
            "WD_%=:\n\t}"
            :: "r"(addr), "r"(parity) : "memory");
    }
}
__device__ __forceinline__ void bulk_copy(uint32_t dst_smem, const void* src, uint32_t bytes,
                                          uint32_t mbar) {
    asm volatile(
        "cp.async.bulk.shared::cta.global.mbarrier::complete_tx::bytes [%0], [%1], %2, [%3];"
        :: "r"(dst_smem), "l"(src), "r"(bytes), "r"(mbar) : "memory");
}

__global__ void __launch_bounds__(NTHREADS, 1)
hs_db_kernel(const float* __restrict__ x,      // (B,T,F,N)
             const float* __restrict__ z0,     // (B,H,N)
             const float* __restrict__ S,      // (B,T,1,N,N)
             const float* __restrict__ aW,     // (H,1,K,F)
             const float* __restrict__ bW,     // (H,1,K,H)
             const float* __restrict__ xBias,  // (H,1)
             const float* __restrict__ zBias,  // (H,1)
             float* __restrict__ out)          // (B,T,H,N)
{
    extern __shared__ float sm[];
    float* sbias = sm + OFF_BIAS;
    __half* sSTh = reinterpret_cast<__half*>(sm + OFF_SST);
    __half* sVh  = reinterpret_cast<__half*>(sm + OFF_V);
    __half* sWh  = reinterpret_cast<__half*>(sm + OFF_W);

    const int tid  = threadIdx.x;
    const int b    = blockIdx.x / CTAS_PER_B;
    const int col0 = (blockIdx.x % CTAS_PER_B) * COLS_PER_CTA;
    const int kc0  = col0 >> 6;           // this CTA's write chunk (64-wide)
    const int cmb  = col0 & 63;           // 0/16/32/48 within chunk

    // mma mapping
    const int wid  = tid >> 5;            // warp 0..7
    const int lane = tid & 31;
    const int gid  = lane >> 2;
    const int tid4 = lane & 3;
    const int l15  = lane & 15;
    const int l16  = lane >> 4;
    // phase-2 tile
    const int mt  = wid >> 1;             // 0..3
    const int ntl = wid & 1;              // 0..1

    const uint32_t smem_u32 = (uint32_t)__cvta_generic_to_shared(sm);
    const uint32_t mbar_base = smem_u32 + OFF_MBAR * 4;      // 3 x 8B
    const uint32_t st_base   = smem_u32 + OFF_STATE * 4;

    // LDSM per-thread address constants (bytes)
    // phase-1 A: slot + aoff[i] + 32*ks + 16*l16
    uint32_t aoff[3];
#pragma unroll
    for (int i = 0; i < 3; ++i)
        aoff[i] = (uint32_t)((16 * (wid + 8 * i) + l15) * (CPITCH_H * 2)) + 16u * l16;
    // phase-1 B: sstB + 128*c + 32*ks   (n row + k-half add folded in)
    const uint32_t sstB = smem_u32 + OFF_SST * 4 +
                          (uint32_t)(((lane & 7) + ((lane >> 4) << 3)) * (PITCH_SST_H * 2)) +
                          (uint32_t)(((lane >> 3) & 1) * 16);
    // phase-2 A: + 32*ks
    const uint32_t p2A = smem_u32 + OFF_W * 4 +
                         (uint32_t)((16 * mt + l15) * (PV_H * 2)) + 16u * l16;
    // phase-2 B: + 32*ks
    const uint32_t p2B = smem_u32 + OFF_V * 4 +
                         (uint32_t)((8 * ntl + (lane & 7)) * (PV_H * 2)) +
                         (uint32_t)(((lane >> 3) & 1) * 16);

    if (tid == 0) {
#pragma unroll
        for (int s = 0; s < NBUF; ++s) mbar_init(mbar_base + 8 * s, 1);
    }

    // Load fused weights once (fp16): sWh[h][0..127]=aW, [128..383]=bW
    for (int i = tid; i < Hn * 128; i += NTHREADS) {
        int h = i >> 7, j = i & 127;
        sWh[h * PV_H + j] = __float2half(aW[i]);
    }
    for (int i = tid; i < Hn * 256; i += NTHREADS) {
        int h = i >> 8, j = i & 255;
        sWh[h * PV_H + 128 + j] = __float2half(bW[i]);
    }
    if (tid < Hn) sbias[tid] = xBias[tid] + zBias[tid];

    // Init: zero this CTA's state columns; sV z-region <- z0 (fp16)
    for (int i = tid; i < SROWS * COLS_PER_CTA; i += NTHREADS) {
        int r = i >> 4, cc = i & 15;
        g_state[0][b][kc0][r][cmb + cc] = __float2half(0.0f);
    }
    for (int i = tid; i < Hn * COLS_PER_CTA; i += NTHREADS) {
        int g = i >> 4, cc = i & 15;
        sVh[cc * PV_H + 128 + g] = __float2half(z0[(b * Hn + g) * Nn + col0 + cc]);
    }

    // TMA ring cursors
    int psl = 0;
    int csl = 0; unsigned cph = 0;

    unsigned lsense = 0;
    grid_barrier(&lsense);   // barrier #1

    for (int t = 0; t < Tn; ++t) {
        const int cur = t & 1;
        const int nxt = cur ^ 1;
        const float* Sbt = S + (size_t)(b * Tn + t) * Nn * Nn;
        const float* xbt = x + (size_t)(b * Tn + t) * Fn * Nn;
        const __half* gst = &g_state[cur][b][0][0][0];

        // prologue: issue chunks 0,1
#pragma unroll
        for (int i = 0; i < 2; ++i) {
            if (tid == 0) {
                mbar_expect_tx(mbar_base + 8 * psl, CHUNK_BYTES);
                bulk_copy(st_base + psl * CHUNK_BYTES,
                          gst + (size_t)i * CHUNK_HALVES, CHUNK_BYTES,
                          mbar_base + 8 * psl);
            }
            psl = (psl + 1 == NBUF) ? 0 : psl + 1;
        }

        // Stage x(t) -> sVh[cc][0..31]
        for (int i = tid; i < Fn * 16; i += NTHREADS) {
            int f = i >> 4, cc = i & 15;
            sVh[cc * PV_H + f] = __float2half(xbt[f * Nn + col0 + cc]);
        }
        // Stage FULL S^T (fp16): 2 k-rows per thread
#pragma unroll
        for (int r2 = 0; r2 < 2; ++r2) {
            const int k = tid + 256 * r2;
            const float* srow = Sbt + (size_t)k * Nn + col0;
            float4 v0 = *reinterpret_cast<const float4*>(srow);
            float4 v1 = *reinterpret_cast<const float4*>(srow + 4);
            float4 v2 = *reinterpret_cast<const float4*>(srow + 8);
            float4 v3 = *reinterpret_cast<const float4*>(srow + 12);
            float vv[16] = {v0.x, v0.y, v0.z, v0.w, v1.x, v1.y, v1.z, v1.w,
                            v2.x, v2.y, v2.z, v2.w, v3.x, v3.y, v3.z, v3.w};
#pragma unroll
            for (int c = 0; c < 16; ++c)
                sSTh[c * PITCH_SST_H + k] = __float2half(vv[c]);
        }
        __syncthreads();                 // S^T + sV.x ready

        // phase-1 accumulators
        float acc[3][2][4];
#pragma unroll
        for (int i = 0; i < 3; ++i)
#pragma unroll
            for (int n = 0; n < 2; ++n)
#pragma unroll
                for (int q = 0; q < 4; ++q) acc[i][n][q] = 0.0f;

        for (int c = 0; c < NCHUNK; ++c) {
            if (c < NCHUNK - 2) {
                if (tid == 0) {
                    mbar_expect_tx(mbar_base + 8 * psl, CHUNK_BYTES);
                    bulk_copy(st_base + psl * CHUNK_BYTES,
                              gst + (size_t)(c + 2) * CHUNK_HALVES, CHUNK_BYTES,
                              mbar_base + 8 * psl);
                }
                psl = (psl + 1 == NBUF) ? 0 : psl + 1;
            }
            const int sl = csl;
            mbar_wait(mbar_base + 8 * sl, cph);
            if (++csl == NBUF) { csl = 0; cph ^= 1u; }
            // compute chunk c: 4 k16-steps, all fragment feeds via LDSM
            {
                const uint32_t slot_addr = st_base + sl * CHUNK_BYTES;
                const uint32_t bB = sstB + 128u * c;
#pragma unroll
                for (int ks = 0; ks < 4; ++ks) {
                    uint32_t b0, b1, b2, b3;
                    ldsm_x4(b0, b1, b2, b3, bB + 32u * ks);   // nt0:{b0,b1} nt1:{b2,b3}
#pragma unroll
                    for (int i = 0; i < 3; ++i) {
                        const int mg = wid + 8 * i;
                        if (mg < 18) {
                            uint32_t a0, a1, a2, a3;
                            ldsm_x4(a0, a1, a2, a3, slot_addr + aoff[i] + 32u * ks);
                            mma_f16(acc[i][0][0], acc[i][0][1], acc[i][0][2], acc[i][0][3],
                                    a0, a1, a2, a3, b0, b1);
                            mma_f16(acc[i][1][0], acc[i][1][1], acc[i][1][2], acc[i][1][3],
                                    a0, a1, a2, a3, b2, b3);
                        }
                    }
                }
            }
            __syncthreads();             // slot-free handoff
        }

        // Write Y (fp16) into col-major sV: row<96 -> j=32+row ; row>=96 -> j=96+row
#pragma unroll
        for (int i = 0; i < 3; ++i) {
            const int mg = wid + 8 * i;
            if (mg < 18) {
                const int r_lo = 16 * mg + gid;
                const int r_hi = r_lo + 8;
                const int j_lo = (r_lo < 96) ? (32 + r_lo) : (96 + r_lo);
                const int j_hi = (r_hi < 96) ? (32 + r_hi) : (96 + r_hi);
#pragma unroll
                for (int nt = 0; nt < 2; ++nt) {
                    const int cl = 8 * nt + 2 * tid4;
                    sVh[cl * PV_H + j_lo]       = __float2half(acc[i][nt][0]);
                    sVh[(cl + 1) * PV_H + j_lo] = __float2half(acc[i][nt][1]);
                    sVh[cl * PV_H + j_hi]       = __float2half(acc[i][nt][2]);
                    sVh[(cl + 1) * PV_H + j_hi] = __float2half(acc[i][nt][3]);
                }
            }
        }
        __syncthreads();

        // ---- Phase 2 via HMMA + LDSM: pre[64,16] = W[64,384] @ V[384,16] ----
        float pd[4] = {0.0f, 0.0f, 0.0f, 0.0f};
#pragma unroll
        for (int ks = 0; ks < 24; ++ks) {
            uint32_t a0, a1, a2, a3, b0, b1;
            ldsm_x4(a0, a1, a2, a3, p2A + 32u * ks);
            ldsm_x2(b0, b1, p2B + 32u * ks);
            mma_f16(pd[0], pd[1], pd[2], pd[3], a0, a1, a2, a3, b0, b1);
        }
        const int h_lo = 16 * mt + gid;
        const int h_hi = h_lo + 8;
        const int c_0  = 8 * ntl + 2 * tid4;
        float z00 = tanhf(sbias[h_lo] + pd[0]);
        float z01 = tanhf(sbias[h_lo] + pd[1]);
        float z10 = tanhf(sbias[h_hi] + pd[2]);
        float z11 = tanhf(sbias[h_hi] + pd[3]);

        // State shift for t+1 (fp16 copy, column-local)
        {
            __half* gnxt = &g_state[nxt][b][kc0][0][0];
#pragma unroll
            for (int it = 0; it < 18; ++it) {
                int i = tid + it * NTHREADS;
                int r = i >> 4, cc = i & 15;
                int j = (r < 96) ? r : (r + 32);
                gnxt[r * CPITCH_H + cmb + cc] = sVh[cc * PV_H + j];
            }
        }
        __syncthreads();   // all reads of z(t-1) done before overwrite

        // write z(t) -> out (fp32) + sV z-region (fp16)
        {
            float* ob = out + ((size_t)(b * Tn + t) * Hn) * Nn + col0;
            ob[(size_t)h_lo * Nn + c_0]     = z00;
            ob[(size_t)h_lo * Nn + c_0 + 1] = z01;
            ob[(size_t)h_hi * Nn + c_0]     = z10;
            ob[(size_t)h_hi * Nn + c_0 + 1] = z11;
            sVh[c_0 * PV_H + 128 + h_lo]       = __float2half(z00);
            sVh[(c_0 + 1) * PV_H + 128 + h_lo] = __float2half(z01);
            sVh[c_0 * PV_H + 128 + h_hi]       = __float2half(z10);
            sVh[(c_0 + 1) * PV_H + 128 + h_hi] = __float2half(z11);
        }

        grid_barrier(&lsense);   // barriers #2..#65
    }

    grid_barrier(&lsense);       // barrier #66 (even parity per launch)
}

extern "C" void kernel_launch(void* const* d_in, const int* in_sizes, int n_in,
                              void* d_out, int out_size) {
    const float* x     = (const float*)d_in[0];
    const float* z0    = (const float*)d_in[1];
    const float* S     = (const float*)d_in[2];
    const float* aW    = (const float*)d_in[3];
    const float* bW    = (const float*)d_in[4];
    const float* xBias = (const float*)d_in[5];
    const float* zBias = (const float*)d_in[6];
    float* out = (float*)d_out;

    cudaFuncSetAttribute(hs_db_kernel,
                         cudaFuncAttributeMaxDynamicSharedMemorySize, SMEM_BYTES);
    hs_db_kernel<<<NCTAS, NTHREADS, SMEM_BYTES>>>(x, z0, S, aW, bW, xBias, zBias, out);
}